// round 1
// baseline (speedup 1.0000x reference)
#include <cuda_runtime.h>
#include <math.h>

// ---------------------------------------------------------------- constants
#define B_    2
#define N_    16384
#define S_    4096
#define D1_   128
#define D2_   256
#define CIN_  397
#define C_    128
#define NCLS  13

// output layout: [x2 (B,128,N)] [featT (B,N,128)] [predT (B,N,13)]
#define OUT0_OFF 0
#define OUT1_OFF (B_ * C_ * N_)          // 4194304
#define OUT2_OFF (OUT1_OFF + B_ * N_ * C_)  // 8388608

// ---------------------------------------------------------------- scratch
__device__ float g_Wfuse[C_ * CIN_];
__device__ float g_bfuse[C_];
__device__ float g_We1[C_ * C_];
__device__ float g_be1[C_];
__device__ float g_We2[C_ * C_];
__device__ float g_be2[C_];
__device__ float g_Wp1[C_ * C_];
__device__ float g_bp1[C_];
__device__ float g_Wp2[NCLS * C_];
__device__ float g_bp2[NCLS];
__device__ float g_ZY[B_ * S_ * C_];     // [b, s, c]  (W2f@points2 + W3f@last_pred)
__device__ int   g_idx[B_ * N_ * 3];
__device__ float g_w[B_ * N_ * 3];
__device__ float g_x[B_ * C_ * N_];      // fuse output
__device__ float g_h[B_ * C_ * N_];      // ext1 output

// ---------------------------------------------------------------- f32x2 helpers
#define PACKF2(d, lo, hi) asm("mov.b64 %0, {%1, %2};" : "=l"(d) : "f"(lo), "f"(hi))
#define UNPACKF2(lo, hi, s) asm("mov.b64 {%0, %1}, %2;" : "=f"(lo), "=f"(hi) : "l"(s))
#define FMAF2(d, a, b, c) asm("fma.rn.f32x2 %0, %1, %2, %3;" : "=l"(d) : "l"(a), "l"(b), "l"(c))

// ---------------------------------------------------------------- BN fold
// bn: [4, Cout] = gamma, beta, mean, var
__global__ void fold_kernel(const float* __restrict__ W, const float* __restrict__ bvec,
                            const float* __restrict__ bn,
                            float* __restrict__ Wf, float* __restrict__ bf,
                            int Cout, int Cin) {
    int total = Cout * Cin;
    for (int i = blockIdx.x * blockDim.x + threadIdx.x; i < total;
         i += gridDim.x * blockDim.x) {
        int o = i / Cin;
        float inv = 1.0f / sqrtf(bn[3 * Cout + o] + 1e-5f);
        float s = bn[o] * inv;
        Wf[i] = W[i] * s;
        if (i - o * Cin == 0) {
            bf[o] = (bvec[o] - bn[2 * Cout + o]) * s + bn[Cout + o];
        }
    }
}

// ---------------------------------------------------------------- 3-NN + weights
__global__ void __launch_bounds__(256) top3_kernel(const float* __restrict__ xyz1,
                                                   const float* __restrict__ xyz2) {
    __shared__ float4 tile[1024];
    const int b = blockIdx.y;
    const int n = blockIdx.x * 256 + threadIdx.x;
    const float* q = xyz1 + ((long)b * N_ + n) * 3;
    const float qx = q[0], qy = q[1], qz = q[2];
    const float sq1 = qx * qx + qy * qy + qz * qz;

    float d0 = 3.4e38f, d1 = 3.4e38f, d2 = 3.4e38f;
    int i0 = 0, i1 = 0, i2 = 0;

    for (int s0 = 0; s0 < S_; s0 += 1024) {
        for (int t = threadIdx.x; t < 1024; t += 256) {
            const float* p = xyz2 + ((long)b * S_ + s0 + t) * 3;
            float x = p[0], y = p[1], z = p[2];
            tile[t] = make_float4(x, y, z, x * x + y * y + z * z);
        }
        __syncthreads();
#pragma unroll 8
        for (int j = 0; j < 1024; ++j) {
            float4 c = tile[j];
            float t = fmaf(qx, c.x, fmaf(qy, c.y, qz * c.z));
            float d = fmaf(-2.0f, t, c.w);   // |x2|^2 - 2 dot   (ordering == full dist)
            if (d < d2) {
                int si = s0 + j;
                if (d < d1) {
                    d2 = d1; i2 = i1;
                    if (d < d0) { d1 = d0; i1 = i0; d0 = d; i0 = si; }
                    else        { d1 = d;  i1 = si; }
                } else { d2 = d; i2 = si; }
            }
        }
        __syncthreads();
    }
    float f0 = d0 + sq1, f1 = d1 + sq1, f2 = d2 + sq1;
    float r0 = 1.0f / (f0 + 1e-8f);
    float r1 = 1.0f / (f1 + 1e-8f);
    float r2 = 1.0f / (f2 + 1e-8f);
    float rs = 1.0f / (r0 + r1 + r2);
    long base = ((long)b * N_ + n) * 3;
    g_idx[base + 0] = i0; g_idx[base + 1] = i1; g_idx[base + 2] = i2;
    g_w[base + 0] = r0 * rs; g_w[base + 1] = r1 * rs; g_w[base + 2] = r2 * rs;
}

// ---------------------------------------------------------------- add last_pred term to ZY
__global__ void addpred_kernel(const float* __restrict__ last_pred) {
    const int b = blockIdx.y;
    const int s = blockIdx.x;
    __shared__ float lp[NCLS];
    if (threadIdx.x < NCLS) lp[threadIdx.x] = last_pred[((long)b * S_ + s) * NCLS + threadIdx.x];
    __syncthreads();
    const int c = threadIdx.x;  // 128 threads
    const float* wr = g_Wfuse + (long)c * CIN_ + (D1_ + D2_);
    float acc = 0.f;
#pragma unroll
    for (int j = 0; j < NCLS; ++j) acc = fmaf(wr[j], lp[j], acc);
    g_ZY[((long)b * S_ + s) * C_ + c] += acc;
}

// ---------------------------------------------------------------- generic 128xN GEMM
// C[m, n] = sum_k A[m, k] * B[k, n]  (+bias, +gather, +res, relu, opt transposed store)
template <bool RELU, bool BIAS, bool RES, bool GATHER, bool TRANS>
__global__ void __launch_bounds__(256) gemm128_kernel(
    const float* __restrict__ A, int lda, int K,
    const float* __restrict__ Bmat, long strideB, int ldb,
    float* __restrict__ C, long strideC, int ldc,
    const float* __restrict__ bias,
    const float* __restrict__ res, long strideRes) {
    const int tid = threadIdx.x;
    const int tx = tid & 15;   // n-group
    const int ty = tid >> 4;   // m-group
    const int b = blockIdx.y;
    const int n0 = blockIdx.x * 128;

    __shared__ float As[16][132];
    __shared__ float Bs[16][128];

    const float* Bb = Bmat + (long)b * strideB + n0;

    unsigned long long acc[8][4];
    unsigned long long zero;
    {
        float z = 0.f;
        PACKF2(zero, z, z);
    }
#pragma unroll
    for (int i = 0; i < 8; ++i)
#pragma unroll
        for (int j = 0; j < 4; ++j) acc[i][j] = zero;

    for (int k0 = 0; k0 < K; k0 += 16) {
#pragma unroll
        for (int i = 0; i < 8; ++i) {
            int idx = tid + i * 256;          // 0..2047
            int mm = idx >> 4, kk = idx & 15;
            As[kk][mm] = A[(long)mm * lda + k0 + kk];
            int kb = idx >> 7, nn = idx & 127;
            Bs[kb][nn] = Bb[(long)(k0 + kb) * ldb + nn];
        }
        __syncthreads();
#pragma unroll
        for (int kk = 0; kk < 16; ++kk) {
            const float4 a0 = *(const float4*)&As[kk][ty * 8];
            const float4 a1 = *(const float4*)&As[kk][ty * 8 + 4];
            const float4 b0 = *(const float4*)&Bs[kk][tx * 8];
            const float4 b1 = *(const float4*)&Bs[kk][tx * 8 + 4];
            unsigned long long bb0, bb1, bb2, bb3;
            PACKF2(bb0, b0.x, b0.y);
            PACKF2(bb1, b0.z, b0.w);
            PACKF2(bb2, b1.x, b1.y);
            PACKF2(bb3, b1.z, b1.w);
            float av[8] = {a0.x, a0.y, a0.z, a0.w, a1.x, a1.y, a1.z, a1.w};
#pragma unroll
            for (int i = 0; i < 8; ++i) {
                unsigned long long aa;
                PACKF2(aa, av[i], av[i]);
                FMAF2(acc[i][0], aa, bb0, acc[i][0]);
                FMAF2(acc[i][1], aa, bb1, acc[i][1]);
                FMAF2(acc[i][2], aa, bb2, acc[i][2]);
                FMAF2(acc[i][3], aa, bb3, acc[i][3]);
            }
        }
        __syncthreads();
    }

    float cv[8][8];
#pragma unroll
    for (int i = 0; i < 8; ++i)
#pragma unroll
        for (int j = 0; j < 4; ++j) UNPACKF2(cv[i][2 * j], cv[i][2 * j + 1], acc[i][j]);

    const int gm = ty * 8;
    if (BIAS) {
#pragma unroll
        for (int i = 0; i < 8; ++i) {
            float bi = bias[gm + i];
#pragma unroll
            for (int j = 0; j < 8; ++j) cv[i][j] += bi;
        }
    }
    if (GATHER) {
#pragma unroll
        for (int j = 0; j < 8; ++j) {
            int n = n0 + tx * 8 + j;
            long base = ((long)b * N_ + n) * 3;
#pragma unroll
            for (int t = 0; t < 3; ++t) {
                int id = g_idx[base + t];
                float w = g_w[base + t];
                const float* z = g_ZY + ((long)b * S_ + id) * C_ + gm;
                float4 z0 = *(const float4*)z;
                float4 z1 = *(const float4*)(z + 4);
                cv[0][j] = fmaf(w, z0.x, cv[0][j]);
                cv[1][j] = fmaf(w, z0.y, cv[1][j]);
                cv[2][j] = fmaf(w, z0.z, cv[2][j]);
                cv[3][j] = fmaf(w, z0.w, cv[3][j]);
                cv[4][j] = fmaf(w, z1.x, cv[4][j]);
                cv[5][j] = fmaf(w, z1.y, cv[5][j]);
                cv[6][j] = fmaf(w, z1.z, cv[6][j]);
                cv[7][j] = fmaf(w, z1.w, cv[7][j]);
            }
        }
    }
    if (RES) {
#pragma unroll
        for (int i = 0; i < 8; ++i) {
            const float* rr = res + (long)b * strideRes + (long)(gm + i) * ldc + n0 + tx * 8;
            float4 r0 = *(const float4*)rr;
            float4 r1 = *(const float4*)(rr + 4);
            cv[i][0] += r0.x; cv[i][1] += r0.y; cv[i][2] += r0.z; cv[i][3] += r0.w;
            cv[i][4] += r1.x; cv[i][5] += r1.y; cv[i][6] += r1.z; cv[i][7] += r1.w;
        }
    }
    if (RELU) {
#pragma unroll
        for (int i = 0; i < 8; ++i)
#pragma unroll
            for (int j = 0; j < 8; ++j) cv[i][j] = fmaxf(cv[i][j], 0.f);
    }
    if (!TRANS) {
#pragma unroll
        for (int i = 0; i < 8; ++i) {
            float* cp = C + (long)b * strideC + (long)(gm + i) * ldc + n0 + tx * 8;
            *(float4*)cp = make_float4(cv[i][0], cv[i][1], cv[i][2], cv[i][3]);
            *(float4*)(cp + 4) = make_float4(cv[i][4], cv[i][5], cv[i][6], cv[i][7]);
        }
    } else {
#pragma unroll
        for (int j = 0; j < 8; ++j) {
            float* cp = C + (long)b * strideC + (long)(n0 + tx * 8 + j) * ldc + gm;
            *(float4*)cp = make_float4(cv[0][j], cv[1][j], cv[2][j], cv[3][j]);
            *(float4*)(cp + 4) = make_float4(cv[4][j], cv[5][j], cv[6][j], cv[7][j]);
        }
    }
}

// ---------------------------------------------------------------- final 13-class head
__global__ void __launch_bounds__(128) pred2_kernel(const float* __restrict__ featT,
                                                    float* __restrict__ outT) {
    __shared__ float fs[16 * 128];
    const long row0 = (long)blockIdx.x * 16;  // global row over B*N
    for (int i = threadIdx.x; i < 16 * 128; i += 128) fs[i] = featT[row0 * 128 + i];
    __syncthreads();
    for (int o = threadIdx.x; o < 16 * NCLS; o += 128) {
        int r = o / NCLS, j = o - r * NCLS;
        const float* wr = g_Wp2 + j * 128;
        const float* fr = fs + r * 128;
        float acc = g_bp2[j];
#pragma unroll 16
        for (int k = 0; k < 128; ++k) acc = fmaf(fr[k], wr[k], acc);
        outT[(row0 + r) * NCLS + j] = fmaxf(acc, 0.f);
    }
}

// ---------------------------------------------------------------- launch
extern "C" void kernel_launch(void* const* d_in, const int* in_sizes, int n_in,
                              void* d_out, int out_size) {
    const float* xyz1      = (const float*)d_in[0];
    const float* xyz2      = (const float*)d_in[1];
    const float* points1   = (const float*)d_in[2];
    const float* points2   = (const float*)d_in[3];
    const float* last_pred = (const float*)d_in[4];
    const float* fuse_W = (const float*)d_in[5];
    const float* fuse_b = (const float*)d_in[6];
    const float* fuse_bn = (const float*)d_in[7];
    const float* e1_W = (const float*)d_in[8];
    const float* e1_b = (const float*)d_in[9];
    const float* e1_bn = (const float*)d_in[10];
    const float* e2_W = (const float*)d_in[11];
    const float* e2_b = (const float*)d_in[12];
    const float* e2_bn = (const float*)d_in[13];
    const float* p1_W = (const float*)d_in[14];
    const float* p1_b = (const float*)d_in[15];
    const float* p1_bn = (const float*)d_in[16];
    const float* p2_W = (const float*)d_in[17];
    const float* p2_b = (const float*)d_in[18];
    const float* p2_bn = (const float*)d_in[19];

    float* out = (float*)d_out;

    float *pWfuse, *pbfuse, *pWe1, *pbe1, *pWe2, *pbe2, *pWp1, *pbp1, *pWp2, *pbp2;
    float *pZY, *px, *ph;
    cudaGetSymbolAddress((void**)&pWfuse, g_Wfuse);
    cudaGetSymbolAddress((void**)&pbfuse, g_bfuse);
    cudaGetSymbolAddress((void**)&pWe1, g_We1);
    cudaGetSymbolAddress((void**)&pbe1, g_be1);
    cudaGetSymbolAddress((void**)&pWe2, g_We2);
    cudaGetSymbolAddress((void**)&pbe2, g_be2);
    cudaGetSymbolAddress((void**)&pWp1, g_Wp1);
    cudaGetSymbolAddress((void**)&pbp1, g_bp1);
    cudaGetSymbolAddress((void**)&pWp2, g_Wp2);
    cudaGetSymbolAddress((void**)&pbp2, g_bp2);
    cudaGetSymbolAddress((void**)&pZY, g_ZY);
    cudaGetSymbolAddress((void**)&px, g_x);
    cudaGetSymbolAddress((void**)&ph, g_h);

    // 1. fold BN into weights
    fold_kernel<<<64, 256>>>(fuse_W, fuse_b, fuse_bn, pWfuse, pbfuse, C_, CIN_);
    fold_kernel<<<64, 256>>>(e1_W, e1_b, e1_bn, pWe1, pbe1, C_, C_);
    fold_kernel<<<64, 256>>>(e2_W, e2_b, e2_bn, pWe2, pbe2, C_, C_);
    fold_kernel<<<64, 256>>>(p1_W, p1_b, p1_bn, pWp1, pbp1, C_, C_);
    fold_kernel<<<8, 256>>>(p2_W, p2_b, p2_bn, pWp2, pbp2, NCLS, C_);

    // 2. 3-NN + interpolation weights
    {
        dim3 grid(N_ / 256, B_);
        top3_kernel<<<grid, 256>>>(xyz1, xyz2);
    }

    // 3. ZY = W2f @ points2 (stored transposed [s, c])
    {
        dim3 grid(S_ / 128, B_);
        gemm128_kernel<false, false, false, false, true><<<grid, 256>>>(
            pWfuse + D1_, CIN_, D2_,
            points2, (long)D2_ * S_, S_,
            pZY, (long)S_ * C_, C_,
            nullptr, nullptr, 0);
    }
    // 3b. ZY += W3f @ last_pred
    {
        dim3 grid(S_, B_);
        addpred_kernel<<<grid, 128>>>(last_pred);
    }

    // 4. fuse: x = relu(W1f @ points1 + bias + gather(ZY))
    {
        dim3 grid(N_ / 128, B_);
        gemm128_kernel<true, true, false, true, false><<<grid, 256>>>(
            pWfuse, CIN_, D1_,
            points1, (long)C_ * N_, N_,
            px, (long)C_ * N_, N_,
            pbfuse, nullptr, 0);
    }
    // 5. ext1: h = relu(We1 @ x + b)
    {
        dim3 grid(N_ / 128, B_);
        gemm128_kernel<true, true, false, false, false><<<grid, 256>>>(
            pWe1, C_, C_,
            px, (long)C_ * N_, N_,
            ph, (long)C_ * N_, N_,
            pbe1, nullptr, 0);
    }
    // 6. ext2: x2 = relu(We2 @ h + b + x)  -> out region 0
    {
        dim3 grid(N_ / 128, B_);
        gemm128_kernel<true, true, true, false, false><<<grid, 256>>>(
            pWe2, C_, C_,
            ph, (long)C_ * N_, N_,
            out + OUT0_OFF, (long)C_ * N_, N_,
            pbe2, px, (long)C_ * N_);
    }
    // 7. pred1: featT = relu(Wp1 @ x2 + b)^T -> out region 1
    {
        dim3 grid(N_ / 128, B_);
        gemm128_kernel<true, true, false, false, true><<<grid, 256>>>(
            pWp1, C_, C_,
            out + OUT0_OFF, (long)C_ * N_, N_,
            out + OUT1_OFF, (long)N_ * C_, C_,
            pbp1, nullptr, 0);
    }
    // 8. pred2: predT = relu(featT @ Wp2^T + b) -> out region 2
    pred2_kernel<<<(B_ * N_) / 16, 128>>>(out + OUT1_OFF, out + OUT2_OFF);
}